// round 1
// baseline (speedup 1.0000x reference)
#include <cuda_runtime.h>
#include <cstdint>

// Problem constants (fixed by setup_inputs)
#define NN 50000
#define DD 512
#define EE 200000

// ---------------- scratch (static __device__ arrays; no allocation) ----------------
__device__ __align__(16) float g_y[(size_t)NN * DD];   // y = x @ W^T + b  (~102.4 MB)
__device__ float g_s[NN];
__device__ float g_t[NN];
__device__ float g_maps[EE];
__device__ float g_diagmaps[NN];
__device__ float g_dinv[NN];
__device__ int   g_deg[NN];
__device__ int   g_off[NN + 1];
__device__ int   g_cursor[NN];
__device__ int   g_csr_col[EE];
__device__ float g_csr_w[EE];

// ---------------- Kernel A: s = x@w1, t = x@w2 (warp per node); also zero accumulators
__global__ void k_node_st(const float* __restrict__ x, const float* __restrict__ w_sheaf) {
    int warp = (blockIdx.x * blockDim.x + threadIdx.x) >> 5;
    int lane = threadIdx.x & 31;
    if (warp >= NN) return;
    const float4* xr = reinterpret_cast<const float4*>(x + (size_t)warp * DD);
    const float4* w1 = reinterpret_cast<const float4*>(w_sheaf);
    const float4* w2 = reinterpret_cast<const float4*>(w_sheaf + DD);
    float s = 0.f, t = 0.f;
#pragma unroll
    for (int i = 0; i < 4; i++) {
        float4 v = xr[lane + 32 * i];
        float4 a = w1[lane + 32 * i];
        float4 b = w2[lane + 32 * i];
        s += v.x * a.x + v.y * a.y + v.z * a.z + v.w * a.w;
        t += v.x * b.x + v.y * b.y + v.z * b.z + v.w * b.w;
    }
#pragma unroll
    for (int o = 16; o; o >>= 1) {
        s += __shfl_xor_sync(0xFFFFFFFFu, s, o);
        t += __shfl_xor_sync(0xFFFFFFFFu, t, o);
    }
    if (lane == 0) {
        g_s[warp] = s;
        g_t[warp] = t;
        g_diagmaps[warp] = 0.f;
        g_deg[warp] = 0;
    }
}

// ---------------- Kernel B: per-edge maps + degree/diag accumulation
__global__ void k_edge_maps(const int* __restrict__ rows, const int* __restrict__ cols) {
    int e = blockIdx.x * blockDim.x + threadIdx.x;
    if (e >= EE) return;
    int r = rows[e], c = cols[e];
    float m = tanhf(g_s[r] + g_t[c]);
    g_maps[e] = m;
    atomicAdd(&g_diagmaps[r], m * m);
    atomicAdd(&g_deg[r], 1);
}

// ---------------- Kernel C: single-block scan of degrees -> CSR offsets; compute d_inv
__global__ void k_scan() {
    __shared__ int s_warp[32];
    int tid = threadIdx.x, lane = tid & 31, wid = tid >> 5;
    int carry = 0;
    for (int base = 0; base < NN; base += 1024) {
        int i = base + tid;
        int v = (i < NN) ? g_deg[i] : 0;
        int xv = v;
#pragma unroll
        for (int o = 1; o < 32; o <<= 1) {
            int y = __shfl_up_sync(0xFFFFFFFFu, xv, o);
            if (lane >= o) xv += y;
        }
        if (lane == 31) s_warp[wid] = xv;
        __syncthreads();
        if (wid == 0) {
            int w = s_warp[lane];
#pragma unroll
            for (int o = 1; o < 32; o <<= 1) {
                int y = __shfl_up_sync(0xFFFFFFFFu, w, o);
                if (lane >= o) w += y;
            }
            s_warp[lane] = w;
        }
        __syncthreads();
        int incl = xv + (wid ? s_warp[wid - 1] : 0);
        if (i < NN) {
            int excl = carry + incl - v;
            g_off[i] = excl;
            g_cursor[i] = excl;
            float dm = g_diagmaps[i];
            g_dinv[i] = rsqrtf(dm + 1.0f);
        }
        int total = s_warp[31];
        __syncthreads();   // protect s_warp before next iteration overwrites
        carry += total;
    }
    if (tid == 0) g_off[NN] = EE;
}

// ---------------- Kernel D: per-edge normalized weight + CSR scatter
__global__ void k_edge_scatter(const int* __restrict__ rows, const int* __restrict__ cols,
                               const int* __restrict__ ridx) {
    int e = blockIdx.x * blockDim.x + threadIdx.x;
    if (e >= EE) return;
    int r = rows[e], c = cols[e];
    float nm = -g_maps[e] * g_maps[ridx[e]] * g_dinv[r] * g_dinv[c];
    int pos = atomicAdd(&g_cursor[r], 1);
    g_csr_col[pos] = c;
    g_csr_w[pos] = nm;
}

// ---------------- GEMM: y = x @ W^T + b using mma.sync tf32 (m16n8k8) ----------------
__device__ __forceinline__ uint32_t f2tf32(float x) {
    uint32_t r;
    asm("cvt.rna.tf32.f32 %0, %1;" : "=r"(r) : "f"(x));
    return r;
}

__device__ __forceinline__ void mma_tf32(float c[4], const uint32_t a[4], const uint32_t b[2]) {
    asm volatile(
        "mma.sync.aligned.m16n8k8.row.col.f32.tf32.tf32.f32 "
        "{%0,%1,%2,%3}, {%4,%5,%6,%7}, {%8,%9}, {%0,%1,%2,%3};\n"
        : "+f"(c[0]), "+f"(c[1]), "+f"(c[2]), "+f"(c[3])
        : "r"(a[0]), "r"(a[1]), "r"(a[2]), "r"(a[3]), "r"(b[0]), "r"(b[1]));
}

#define BM 128
#define BN 128
#define BK 16
#define SKEW 4

__global__ __launch_bounds__(256) void k_gemm(const float* __restrict__ A,
                                              const float* __restrict__ W,
                                              const float* __restrict__ bias) {
    __shared__ float As[BM][BK + SKEW];
    __shared__ float Bs[BN][BK + SKEW];
    int tid = threadIdx.x;
    int wid = tid >> 5, lane = tid & 31;
    int row0 = blockIdx.y * BM;
    int col0 = blockIdx.x * BN;

    int warp_m = (wid & 3) * 32;   // 4 warps along M -> 128
    int warp_n = (wid >> 2) * 64;  // 2 warps along N -> 128

    float acc[2][8][4];
#pragma unroll
    for (int mi = 0; mi < 2; mi++)
#pragma unroll
        for (int ni = 0; ni < 8; ni++)
#pragma unroll
            for (int q = 0; q < 4; q++) acc[mi][ni][q] = 0.f;

    for (int k0 = 0; k0 < DD; k0 += BK) {
        // load tiles: 128x16 floats each = 512 float4; 256 threads * 2
#pragma unroll
        for (int l = 0; l < 2; l++) {
            int f = tid + l * 256;         // 0..511
            int r = f >> 2;                // 0..127
            int c = (f & 3) << 2;          // 0,4,8,12
            int gr = row0 + r;
            float4 av = (gr < NN) ? *reinterpret_cast<const float4*>(A + (size_t)gr * DD + k0 + c)
                                  : make_float4(0.f, 0.f, 0.f, 0.f);
            *reinterpret_cast<float4*>(&As[r][c]) = av;
            float4 wv = *reinterpret_cast<const float4*>(W + (size_t)(col0 + r) * DD + k0 + c);
            *reinterpret_cast<float4*>(&Bs[r][c]) = wv;
        }
        __syncthreads();

#pragma unroll
        for (int kk = 0; kk < BK; kk += 8) {
            uint32_t afrag[2][4];
#pragma unroll
            for (int mi = 0; mi < 2; mi++) {
                int mrow = warp_m + mi * 16 + (lane >> 2);
                int kc = kk + (lane & 3);
                afrag[mi][0] = f2tf32(As[mrow][kc]);
                afrag[mi][1] = f2tf32(As[mrow + 8][kc]);
                afrag[mi][2] = f2tf32(As[mrow][kc + 4]);
                afrag[mi][3] = f2tf32(As[mrow + 8][kc + 4]);
            }
            uint32_t bfrag[8][2];
#pragma unroll
            for (int ni = 0; ni < 8; ni++) {
                int nrow = warp_n + ni * 8 + (lane >> 2);
                int kc = kk + (lane & 3);
                bfrag[ni][0] = f2tf32(Bs[nrow][kc]);
                bfrag[ni][1] = f2tf32(Bs[nrow][kc + 4]);
            }
#pragma unroll
            for (int mi = 0; mi < 2; mi++)
#pragma unroll
                for (int ni = 0; ni < 8; ni++) mma_tf32(acc[mi][ni], afrag[mi], bfrag[ni]);
        }
        __syncthreads();
    }

    // epilogue: add bias, store to g_y
#pragma unroll
    for (int mi = 0; mi < 2; mi++) {
        int r0 = row0 + warp_m + mi * 16 + (lane >> 2);
#pragma unroll
        for (int ni = 0; ni < 8; ni++) {
            int cb = col0 + warp_n + ni * 8 + 2 * (lane & 3);
            float b0 = bias[cb], b1 = bias[cb + 1];
            if (r0 < NN) {
                float2 v = make_float2(acc[mi][ni][0] + b0, acc[mi][ni][1] + b1);
                *reinterpret_cast<float2*>(&g_y[(size_t)r0 * DD + cb]) = v;
            }
            if (r0 + 8 < NN) {
                float2 v = make_float2(acc[mi][ni][2] + b0, acc[mi][ni][3] + b1);
                *reinterpret_cast<float2*>(&g_y[(size_t)(r0 + 8) * DD + cb]) = v;
            }
        }
    }
}

// ---------------- Kernel F: warp-per-node CSR gather aggregation + residual update
__global__ void k_aggregate(const float* __restrict__ x, float* __restrict__ out) {
    int warp = (blockIdx.x * blockDim.x + threadIdx.x) >> 5;
    int lane = threadIdx.x & 31;
    if (warp >= NN) return;
    int n = warp;
    float dm = g_diagmaps[n];
    float diag = dm / (dm + 1.0f);   // == d_inv * diag_maps * d_inv

    const float4* yn = reinterpret_cast<const float4*>(g_y + (size_t)n * DD);
    float4 acc[4];
#pragma unroll
    for (int i = 0; i < 4; i++) {
        float4 v = yn[lane + 32 * i];
        acc[i].x = diag * v.x;
        acc[i].y = diag * v.y;
        acc[i].z = diag * v.z;
        acc[i].w = diag * v.w;
    }
    int e0 = g_off[n], e1 = g_off[n + 1];
    for (int e = e0; e < e1; e++) {
        int c = g_csr_col[e];
        float w = g_csr_w[e];
        const float4* yc = reinterpret_cast<const float4*>(g_y + (size_t)c * DD);
#pragma unroll
        for (int i = 0; i < 4; i++) {
            float4 v = yc[lane + 32 * i];
            acc[i].x += w * v.x;
            acc[i].y += w * v.y;
            acc[i].z += w * v.z;
            acc[i].w += w * v.w;
        }
    }
    const float4* xr = reinterpret_cast<const float4*>(x + (size_t)n * DD);
    float4* o = reinterpret_cast<float4*>(out) + (size_t)n * (DD / 4);
#pragma unroll
    for (int i = 0; i < 4; i++) {
        float4 xv = xr[lane + 32 * i];
        float4 r;
        r.x = xv.x - 0.5f * acc[i].x;
        r.y = xv.y - 0.5f * acc[i].y;
        r.z = xv.z - 0.5f * acc[i].z;
        r.w = xv.w - 0.5f * acc[i].w;
        o[lane + 32 * i] = r;
    }
}

// ---------------- launch ----------------
extern "C" void kernel_launch(void* const* d_in, const int* in_sizes, int n_in,
                              void* d_out, int out_size) {
    const float* x    = (const float*)d_in[0];
    const float* W    = (const float*)d_in[1];
    const float* b    = (const float*)d_in[2];
    const float* ws   = (const float*)d_in[3];
    const int*   ei   = (const int*)d_in[4];   // [2, EE] row-major: first EE = row, next EE = col
    const int*   ridx = (const int*)d_in[5];
    const int* rows = ei;
    const int* cols = ei + EE;
    float* out = (float*)d_out;

    k_node_st<<<(NN * 32 + 255) / 256, 256>>>(x, ws);
    k_edge_maps<<<(EE + 255) / 256, 256>>>(rows, cols);
    k_scan<<<1, 1024>>>();
    k_edge_scatter<<<(EE + 255) / 256, 256>>>(rows, cols, ridx);

    dim3 ggrid(DD / BN, (NN + BM - 1) / BM);
    k_gemm<<<ggrid, 256>>>(x, W, b);

    k_aggregate<<<(NN * 32 + 255) / 256, 256>>>(x, out);
}

// round 2
// speedup vs baseline: 1.1542x; 1.1542x over previous
#include <cuda_runtime.h>
#include <cstdint>

// Problem constants (fixed by setup_inputs)
#define NN 50000
#define DD 512
#define EE 200000

// ---------------- scratch (static __device__ arrays; no allocation) ----------------
__device__ __align__(16) float g_y[(size_t)NN * DD];   // y = x @ W^T + b  (~102.4 MB)
__device__ float g_s[NN];
__device__ float g_t[NN];
__device__ float g_maps[EE];
__device__ float g_diagmaps[NN];
__device__ float g_dinv[NN];
__device__ int   g_deg[NN];
__device__ int   g_off[NN + 1];
__device__ int   g_cursor[NN];
__device__ int   g_csr_col[EE];
__device__ float g_csr_w[EE];

// ---------------- Kernel A: s = x@w1, t = x@w2 (warp per node); also zero accumulators
__global__ void k_node_st(const float* __restrict__ x, const float* __restrict__ w_sheaf) {
    int warp = (blockIdx.x * blockDim.x + threadIdx.x) >> 5;
    int lane = threadIdx.x & 31;
    if (warp >= NN) return;
    const float4* xr = reinterpret_cast<const float4*>(x + (size_t)warp * DD);
    const float4* w1 = reinterpret_cast<const float4*>(w_sheaf);
    const float4* w2 = reinterpret_cast<const float4*>(w_sheaf + DD);
    float s = 0.f, t = 0.f;
#pragma unroll
    for (int i = 0; i < 4; i++) {
        float4 v = xr[lane + 32 * i];
        float4 a = w1[lane + 32 * i];
        float4 b = w2[lane + 32 * i];
        s += v.x * a.x + v.y * a.y + v.z * a.z + v.w * a.w;
        t += v.x * b.x + v.y * b.y + v.z * b.z + v.w * b.w;
    }
#pragma unroll
    for (int o = 16; o; o >>= 1) {
        s += __shfl_xor_sync(0xFFFFFFFFu, s, o);
        t += __shfl_xor_sync(0xFFFFFFFFu, t, o);
    }
    if (lane == 0) {
        g_s[warp] = s;
        g_t[warp] = t;
        g_diagmaps[warp] = 0.f;
        g_deg[warp] = 0;
    }
}

// ---------------- Kernel B: per-edge maps + degree/diag accumulation
__global__ void k_edge_maps(const int* __restrict__ rows, const int* __restrict__ cols) {
    int e = blockIdx.x * blockDim.x + threadIdx.x;
    if (e >= EE) return;
    int r = rows[e], c = cols[e];
    float m = tanhf(g_s[r] + g_t[c]);
    g_maps[e] = m;
    atomicAdd(&g_diagmaps[r], m * m);
    atomicAdd(&g_deg[r], 1);
}

// ---------------- Kernel C: thread-chunked single-block scan -> CSR offsets + d_inv
__global__ __launch_bounds__(1024) void k_scan() {
    __shared__ int s_warp[32];
    const int CH = (NN + 1023) / 1024;  // 49
    int tid = threadIdx.x, lane = tid & 31, wid = tid >> 5;
    int base = tid * CH;
    // phase 1: per-thread sum
    int sum = 0;
#pragma unroll 7
    for (int i = 0; i < CH; i++) {
        int idx = base + i;
        if (idx < NN) sum += g_deg[idx];
    }
    // block exclusive scan of per-thread sums
    int v = sum;
#pragma unroll
    for (int o = 1; o < 32; o <<= 1) {
        int y = __shfl_up_sync(0xFFFFFFFFu, v, o);
        if (lane >= o) v += y;
    }
    if (lane == 31) s_warp[wid] = v;
    __syncthreads();
    if (wid == 0) {
        int w = s_warp[lane];
#pragma unroll
        for (int o = 1; o < 32; o <<= 1) {
            int y = __shfl_up_sync(0xFFFFFFFFu, w, o);
            if (lane >= o) w += y;
        }
        s_warp[lane] = w;
    }
    __syncthreads();
    int run = v - sum + (wid ? s_warp[wid - 1] : 0);  // exclusive prefix
    // phase 2: local prefix writeback + d_inv
    for (int i = 0; i < CH; i++) {
        int idx = base + i;
        if (idx < NN) {
            int d = g_deg[idx];
            g_off[idx] = run;
            g_cursor[idx] = run;
            g_dinv[idx] = rsqrtf(g_diagmaps[idx] + 1.0f);
            run += d;
        }
    }
    if (tid == 0) g_off[NN] = EE;
}

// ---------------- Kernel D: per-edge normalized weight + CSR scatter
__global__ void k_edge_scatter(const int* __restrict__ rows, const int* __restrict__ cols,
                               const int* __restrict__ ridx) {
    int e = blockIdx.x * blockDim.x + threadIdx.x;
    if (e >= EE) return;
    int r = rows[e], c = cols[e];
    float nm = -g_maps[e] * g_maps[ridx[e]] * g_dinv[r] * g_dinv[c];
    int pos = atomicAdd(&g_cursor[r], 1);
    g_csr_col[pos] = c;
    g_csr_w[pos] = nm;
}

// ---------------- GEMM: y = x @ W^T + b, tf32 mma.sync, cp.async double-buffered ----
__device__ __forceinline__ void mma_tf32(float c[4], const uint32_t a[4], const uint32_t b[2]) {
    asm volatile(
        "mma.sync.aligned.m16n8k8.row.col.f32.tf32.tf32.f32 "
        "{%0,%1,%2,%3}, {%4,%5,%6,%7}, {%8,%9}, {%0,%1,%2,%3};\n"
        : "+f"(c[0]), "+f"(c[1]), "+f"(c[2]), "+f"(c[3])
        : "r"(a[0]), "r"(a[1]), "r"(a[2]), "r"(a[3]), "r"(b[0]), "r"(b[1]));
}

__device__ __forceinline__ void cp_async16(uint32_t s, const void* g, int src_size) {
    asm volatile("cp.async.cg.shared.global [%0], [%1], 16, %2;\n"
                 :: "r"(s), "l"(g), "r"(src_size));
}
__device__ __forceinline__ void cp_commit() { asm volatile("cp.async.commit_group;\n"); }
template <int W> __device__ __forceinline__ void cp_wait() {
    asm volatile("cp.async.wait_group %0;\n" :: "n"(W));
}

#define BM 128
#define BN 128
#define BK 32
#define ASTRIDE 36              // 32 + 4 floats pad (16B-aligned rows, conflict-free frags)
#define STG_MAT (128 * ASTRIDE) // floats per matrix per stage
#define STG (2 * STG_MAT)       // floats per stage (A + B)
#define GEMM_SMEM (2 * STG * 4) // bytes: 73728

__device__ __forceinline__ void load_stage(float* Asm, float* Bsm,
                                           const float* __restrict__ A,
                                           const float* __restrict__ W,
                                           int row0, int col0, int k0, int tid) {
#pragma unroll
    for (int i = 0; i < 4; i++) {
        int idx = tid + i * 256;       // 0..1023
        int r = idx >> 3;              // 0..127
        int c = (idx & 7) << 2;        // 0,4,...,28
        int gr = row0 + r;
        int ok = (gr < NN);
        const float* src_a = A + (size_t)(ok ? gr : 0) * DD + k0 + c;
        uint32_t sa = (uint32_t)__cvta_generic_to_shared(Asm + r * ASTRIDE + c);
        cp_async16(sa, src_a, ok ? 16 : 0);
        const float* src_b = W + (size_t)(col0 + r) * DD + k0 + c;
        uint32_t sb = (uint32_t)__cvta_generic_to_shared(Bsm + r * ASTRIDE + c);
        cp_async16(sb, src_b, 16);
    }
}

__global__ __launch_bounds__(256) void k_gemm(const float* __restrict__ A,
                                              const float* __restrict__ W,
                                              const float* __restrict__ bias) {
    extern __shared__ float sm[];
    int tid = threadIdx.x;
    int wid = tid >> 5, lane = tid & 31;
    int row0 = blockIdx.y * BM;
    int col0 = blockIdx.x * BN;

    int warp_m = (wid & 3) * 32;   // 4 warps along M -> 128
    int warp_n = (wid >> 2) * 64;  // 2 warps along N -> 128

    float acc[2][8][4];
#pragma unroll
    for (int mi = 0; mi < 2; mi++)
#pragma unroll
        for (int ni = 0; ni < 8; ni++)
#pragma unroll
            for (int q = 0; q < 4; q++) acc[mi][ni][q] = 0.f;

    const int NIT = DD / BK;  // 16
    load_stage(sm, sm + STG_MAT, A, W, row0, col0, 0, tid);
    cp_commit();

    for (int it = 0; it < NIT; it++) {
        if (it + 1 < NIT) {
            float* base = sm + ((it + 1) & 1) * STG;
            load_stage(base, base + STG_MAT, A, W, row0, col0, (it + 1) * BK, tid);
            cp_commit();
            cp_wait<1>();
        } else {
            cp_wait<0>();
        }
        __syncthreads();

        const float* Asb = sm + (it & 1) * STG;
        const float* Bsb = Asb + STG_MAT;

#pragma unroll
        for (int kk = 0; kk < BK; kk += 8) {
            uint32_t afrag[2][4];
#pragma unroll
            for (int mi = 0; mi < 2; mi++) {
                int mrow = warp_m + mi * 16 + (lane >> 2);
                int kc = kk + (lane & 3);
                afrag[mi][0] = __float_as_uint(Asb[mrow * ASTRIDE + kc]);
                afrag[mi][1] = __float_as_uint(Asb[(mrow + 8) * ASTRIDE + kc]);
                afrag[mi][2] = __float_as_uint(Asb[mrow * ASTRIDE + kc + 4]);
                afrag[mi][3] = __float_as_uint(Asb[(mrow + 8) * ASTRIDE + kc + 4]);
            }
            uint32_t bfrag[8][2];
#pragma unroll
            for (int ni = 0; ni < 8; ni++) {
                int nrow = warp_n + ni * 8 + (lane >> 2);
                int kc = kk + (lane & 3);
                bfrag[ni][0] = __float_as_uint(Bsb[nrow * ASTRIDE + kc]);
                bfrag[ni][1] = __float_as_uint(Bsb[nrow * ASTRIDE + kc + 4]);
            }
#pragma unroll
            for (int mi = 0; mi < 2; mi++)
#pragma unroll
                for (int ni = 0; ni < 8; ni++) mma_tf32(acc[mi][ni], afrag[mi], bfrag[ni]);
        }
        __syncthreads();
    }

    // epilogue: add bias, store to g_y
#pragma unroll
    for (int mi = 0; mi < 2; mi++) {
        int r0 = row0 + warp_m + mi * 16 + (lane >> 2);
#pragma unroll
        for (int ni = 0; ni < 8; ni++) {
            int cb = col0 + warp_n + ni * 8 + 2 * (lane & 3);
            float b0 = bias[cb], b1 = bias[cb + 1];
            if (r0 < NN) {
                float2 v = make_float2(acc[mi][ni][0] + b0, acc[mi][ni][1] + b1);
                *reinterpret_cast<float2*>(&g_y[(size_t)r0 * DD + cb]) = v;
            }
            if (r0 + 8 < NN) {
                float2 v = make_float2(acc[mi][ni][2] + b0, acc[mi][ni][3] + b1);
                *reinterpret_cast<float2*>(&g_y[(size_t)(r0 + 8) * DD + cb]) = v;
            }
        }
    }
}

// ---------------- Kernel F: warp-per-node CSR gather aggregation + residual update
__global__ void k_aggregate(const float* __restrict__ x, float* __restrict__ out) {
    int warp = (blockIdx.x * blockDim.x + threadIdx.x) >> 5;
    int lane = threadIdx.x & 31;
    if (warp >= NN) return;
    int n = warp;
    float dm = g_diagmaps[n];
    float diag = dm / (dm + 1.0f);   // == d_inv * diag_maps * d_inv

    const float4* yn = reinterpret_cast<const float4*>(g_y + (size_t)n * DD);
    float4 acc[4];
#pragma unroll
    for (int i = 0; i < 4; i++) {
        float4 v = yn[lane + 32 * i];
        acc[i].x = diag * v.x;
        acc[i].y = diag * v.y;
        acc[i].z = diag * v.z;
        acc[i].w = diag * v.w;
    }
    int e0 = g_off[n], e1 = g_off[n + 1];
    for (int e = e0; e < e1; e++) {
        int c = g_csr_col[e];
        float w = g_csr_w[e];
        const float4* yc = reinterpret_cast<const float4*>(g_y + (size_t)c * DD);
#pragma unroll
        for (int i = 0; i < 4; i++) {
            float4 v = yc[lane + 32 * i];
            acc[i].x += w * v.x;
            acc[i].y += w * v.y;
            acc[i].z += w * v.z;
            acc[i].w += w * v.w;
        }
    }
    const float4* xr = reinterpret_cast<const float4*>(x + (size_t)n * DD);
    float4* o = reinterpret_cast<float4*>(out) + (size_t)n * (DD / 4);
#pragma unroll
    for (int i = 0; i < 4; i++) {
        float4 xv = xr[lane + 32 * i];
        float4 r;
        r.x = xv.x - 0.5f * acc[i].x;
        r.y = xv.y - 0.5f * acc[i].y;
        r.z = xv.z - 0.5f * acc[i].z;
        r.w = xv.w - 0.5f * acc[i].w;
        o[lane + 32 * i] = r;
    }
}

// ---------------- launch ----------------
extern "C" void kernel_launch(void* const* d_in, const int* in_sizes, int n_in,
                              void* d_out, int out_size) {
    const float* x    = (const float*)d_in[0];
    const float* W    = (const float*)d_in[1];
    const float* b    = (const float*)d_in[2];
    const float* ws   = (const float*)d_in[3];
    const int*   ei   = (const int*)d_in[4];   // [2, EE]: first EE = row, next EE = col
    const int*   ridx = (const int*)d_in[5];
    const int* rows = ei;
    const int* cols = ei + EE;
    float* out = (float*)d_out;

    static int smem_set = 0;
    if (!smem_set) {
        cudaFuncSetAttribute(k_gemm, cudaFuncAttributeMaxDynamicSharedMemorySize, GEMM_SMEM);
        smem_set = 1;
    }

    k_node_st<<<(NN * 32 + 255) / 256, 256>>>(x, ws);
    k_edge_maps<<<(EE + 255) / 256, 256>>>(rows, cols);
    k_scan<<<1, 1024>>>();
    k_edge_scatter<<<(EE + 255) / 256, 256>>>(rows, cols, ridx);

    dim3 ggrid(DD / BN, (NN + BM - 1) / BM);
    k_gemm<<<ggrid, 256, GEMM_SMEM>>>(x, W, b);

    k_aggregate<<<(NN * 32 + 255) / 256, 256>>>(x, out);
}

// round 6
// speedup vs baseline: 1.3349x; 1.1565x over previous
#include <cuda_runtime.h>
#include <cuda_fp16.h>
#include <cstdint>

// Problem constants (fixed by setup_inputs)
#define NN 50000
#define DD 512
#define EE 200000

// ---------------- scratch (static __device__ arrays; no allocation) ----------------
__device__ __align__(16) float  g_y[(size_t)NN * DD];     // y = x @ W^T + b (~102.4 MB)
__device__ __align__(16) __half g_xh[(size_t)NN * DD];    // fp16 copy of x (~51.2 MB)
__device__ __align__(16) __half g_wh[(size_t)DD * DD];    // fp16 copy of W (0.5 MB)
__device__ float g_s[NN];
__device__ float g_t[NN];
__device__ float g_maps[EE];
__device__ float g_diagmaps[NN];
__device__ float g_dinv[NN];
__device__ int   g_deg[NN];
__device__ int   g_off[NN + 1];
__device__ int   g_cursor[NN];
__device__ int   g_csr_col[EE];
__device__ float g_csr_w[EE];

// ---------------- Kernel A: s = x@w1, t = x@w2 (warp per node); fp16 convert of x;
//                  also zero accumulators
__global__ void k_node_st(const float* __restrict__ x, const float* __restrict__ w_sheaf) {
    int warp = (blockIdx.x * blockDim.x + threadIdx.x) >> 5;
    int lane = threadIdx.x & 31;
    if (warp >= NN) return;
    const float4* xr = reinterpret_cast<const float4*>(x + (size_t)warp * DD);
    const float4* w1 = reinterpret_cast<const float4*>(w_sheaf);
    const float4* w2 = reinterpret_cast<const float4*>(w_sheaf + DD);
    __half2* xh = reinterpret_cast<__half2*>(g_xh + (size_t)warp * DD);
    float s = 0.f, t = 0.f;
#pragma unroll
    for (int i = 0; i < 4; i++) {
        float4 v = xr[lane + 32 * i];
        float4 a = w1[lane + 32 * i];
        float4 b = w2[lane + 32 * i];
        s += v.x * a.x + v.y * a.y + v.z * a.z + v.w * a.w;
        t += v.x * b.x + v.y * b.y + v.z * b.z + v.w * b.w;
        int p = (lane + 32 * i) * 2;
        xh[p]     = __floats2half2_rn(v.x, v.y);
        xh[p + 1] = __floats2half2_rn(v.z, v.w);
    }
#pragma unroll
    for (int o = 16; o; o >>= 1) {
        s += __shfl_xor_sync(0xFFFFFFFFu, s, o);
        t += __shfl_xor_sync(0xFFFFFFFFu, t, o);
    }
    if (lane == 0) {
        g_s[warp] = s;
        g_t[warp] = t;
        g_diagmaps[warp] = 0.f;
        g_deg[warp] = 0;
    }
}

// ---------------- tiny kernel: W -> fp16
__global__ void k_wconv(const float* __restrict__ W) {
    int i = blockIdx.x * blockDim.x + threadIdx.x;   // over DD*DD/4
    const float4* src = reinterpret_cast<const float4*>(W);
    __half2* dst = reinterpret_cast<__half2*>(g_wh);
    float4 v = src[i];
    dst[2 * i]     = __floats2half2_rn(v.x, v.y);
    dst[2 * i + 1] = __floats2half2_rn(v.z, v.w);
}

// ---------------- Kernel B: per-edge maps + degree/diag accumulation
__global__ void k_edge_maps(const int* __restrict__ rows, const int* __restrict__ cols) {
    int e = blockIdx.x * blockDim.x + threadIdx.x;
    if (e >= EE) return;
    int r = rows[e], c = cols[e];
    float m = tanhf(g_s[r] + g_t[c]);
    g_maps[e] = m;
    atomicAdd(&g_diagmaps[r], m * m);
    atomicAdd(&g_deg[r], 1);
}

// ---------------- Kernel C: thread-chunked single-block scan -> CSR offsets + d_inv
__global__ __launch_bounds__(1024) void k_scan() {
    __shared__ int s_warp[32];
    const int CH = (NN + 1023) / 1024;  // 49
    int tid = threadIdx.x, lane = tid & 31, wid = tid >> 5;
    int base = tid * CH;
    int sum = 0;
#pragma unroll 7
    for (int i = 0; i < CH; i++) {
        int idx = base + i;
        if (idx < NN) sum += g_deg[idx];
    }
    int v = sum;
#pragma unroll
    for (int o = 1; o < 32; o <<= 1) {
        int y = __shfl_up_sync(0xFFFFFFFFu, v, o);
        if (lane >= o) v += y;
    }
    if (lane == 31) s_warp[wid] = v;
    __syncthreads();
    if (wid == 0) {
        int w = s_warp[lane];
#pragma unroll
        for (int o = 1; o < 32; o <<= 1) {
            int y = __shfl_up_sync(0xFFFFFFFFu, w, o);
            if (lane >= o) w += y;
        }
        s_warp[lane] = w;
    }
    __syncthreads();
    int run = v - sum + (wid ? s_warp[wid - 1] : 0);
    for (int i = 0; i < CH; i++) {
        int idx = base + i;
        if (idx < NN) {
            int d = g_deg[idx];
            g_off[idx] = run;
            g_cursor[idx] = run;
            g_dinv[idx] = rsqrtf(g_diagmaps[idx] + 1.0f);
            run += d;
        }
    }
    if (tid == 0) g_off[NN] = EE;
}

// ---------------- Kernel D: per-edge normalized weight + CSR scatter
__global__ void k_edge_scatter(const int* __restrict__ rows, const int* __restrict__ cols,
                               const int* __restrict__ ridx) {
    int e = blockIdx.x * blockDim.x + threadIdx.x;
    if (e >= EE) return;
    int r = rows[e], c = cols[e];
    float nm = -g_maps[e] * g_maps[ridx[e]] * g_dinv[r] * g_dinv[c];
    int pos = atomicAdd(&g_cursor[r], 1);
    g_csr_col[pos] = c;
    g_csr_w[pos] = nm;
}

// ========== GEMM: y = x @ W^T + b, fp16 mma.sync m16n8k16, cp.async double-buffered ====
__device__ __forceinline__ void mma_f16(float c[4], const uint32_t a[4], const uint32_t b[2]) {
    asm volatile(
        "mma.sync.aligned.m16n8k16.row.col.f32.f16.f16.f32 "
        "{%0,%1,%2,%3}, {%4,%5,%6,%7}, {%8,%9}, {%0,%1,%2,%3};\n"
        : "+f"(c[0]), "+f"(c[1]), "+f"(c[2]), "+f"(c[3])
        : "r"(a[0]), "r"(a[1]), "r"(a[2]), "r"(a[3]), "r"(b[0]), "r"(b[1]));
}

__device__ __forceinline__ void cp_async16(uint32_t s, const void* g, int src_size) {
    asm volatile("cp.async.cg.shared.global [%0], [%1], 16, %2;\n"
                 :: "r"(s), "l"(g), "r"(src_size));
}
__device__ __forceinline__ void cp_commit() { asm volatile("cp.async.commit_group;\n"); }
template <int W> __device__ __forceinline__ void cp_wait() {
    asm volatile("cp.async.wait_group %0;\n" :: "n"(W));
}

#define BM 128
#define BN 128
#define BK 32
#define HS 40                   // half stride per row: 32 + 8 pad (80B, bank-conflict-free)
#define STG_MAT (128 * HS)      // halves per matrix per stage
#define STG (2 * STG_MAT)       // halves per stage (A + B)

__device__ __forceinline__ void load_stage_f16(__half* Asm, __half* Bsm,
                                               const __half* __restrict__ A,
                                               const __half* __restrict__ W,
                                               int row0, int col0, int k0, int tid) {
    // each matrix tile: 128 rows x 32 halves = 64B/row = 4 x 16B chunks; 512 chunks
#pragma unroll
    for (int i = 0; i < 2; i++) {
        int q = tid + i * 256;          // 0..511
        int r = q >> 2;                 // 0..127
        int c8 = (q & 3) << 3;          // 0,8,16,24 (halves)
        int gr = row0 + r;
        int ok = (gr < NN);
        const __half* src_a = A + (size_t)(ok ? gr : 0) * DD + k0 + c8;
        cp_async16((uint32_t)__cvta_generic_to_shared(Asm + r * HS + c8), src_a, ok ? 16 : 0);
        const __half* src_b = W + (size_t)(col0 + r) * DD + k0 + c8;
        cp_async16((uint32_t)__cvta_generic_to_shared(Bsm + r * HS + c8), src_b, 16);
    }
}

__global__ __launch_bounds__(256) void k_gemm(const float* __restrict__ bias) {
    __shared__ __half sm[2 * STG];
    int tid = threadIdx.x;
    int wid = tid >> 5, lane = tid & 31;
    int row0 = blockIdx.y * BM;
    int col0 = blockIdx.x * BN;

    int warp_m = (wid & 3) * 32;   // 4 warps along M -> 128
    int warp_n = (wid >> 2) * 64;  // 2 warps along N -> 128
    int g = lane >> 2;             // 0..7
    int t2 = (lane & 3) * 2;       // 0,2,4,6

    float acc[2][8][4];
#pragma unroll
    for (int mi = 0; mi < 2; mi++)
#pragma unroll
        for (int ni = 0; ni < 8; ni++)
#pragma unroll
            for (int q = 0; q < 4; q++) acc[mi][ni][q] = 0.f;

    const int NIT = DD / BK;  // 16
    load_stage_f16(sm, sm + STG_MAT, g_xh, g_wh, row0, col0, 0, tid);
    cp_commit();

    for (int it = 0; it < NIT; it++) {
        if (it + 1 < NIT) {
            __half* base = sm + ((it + 1) & 1) * STG;
            load_stage_f16(base, base + STG_MAT, g_xh, g_wh, row0, col0, (it + 1) * BK, tid);
            cp_commit();
            cp_wait<1>();
        } else {
            cp_wait<0>();
        }
        __syncthreads();

        const __half* Asb = sm + (it & 1) * STG;
        const __half* Bsb = Asb + STG_MAT;

#pragma unroll
        for (int kk = 0; kk < BK; kk += 16) {
            uint32_t afrag[2][4];
#pragma unroll
            for (int mi = 0; mi < 2; mi++) {
                int mrow = warp_m + mi * 16 + g;
                int kc = kk + t2;
                afrag[mi][0] = *reinterpret_cast<const uint32_t*>(&Asb[mrow * HS + kc]);
                afrag[mi][1] = *reinterpret_cast<const uint32_t*>(&Asb[(mrow + 8) * HS + kc]);
                afrag[mi][2] = *reinterpret_cast<const uint32_t*>(&Asb[mrow * HS + kc + 8]);
                afrag[mi][3] = *reinterpret_cast<const uint32_t*>(&Asb[(mrow + 8) * HS + kc + 8]);
            }
            uint32_t bfrag[8][2];
#pragma unroll
            for (int ni = 0; ni < 8; ni++) {
                int nrow = warp_n + ni * 8 + g;
                int kc = kk + t2;
                bfrag[ni][0] = *reinterpret_cast<const uint32_t*>(&Bsb[nrow * HS + kc]);
                bfrag[ni][1] = *reinterpret_cast<const uint32_t*>(&Bsb[nrow * HS + kc + 8]);
            }
#pragma unroll
            for (int mi = 0; mi < 2; mi++)
#pragma unroll
                for (int ni = 0; ni < 8; ni++) mma_f16(acc[mi][ni], afrag[mi], bfrag[ni]);
        }
        __syncthreads();
    }

    // epilogue: add bias, store to g_y
#pragma unroll
    for (int mi = 0; mi < 2; mi++) {
        int r0 = row0 + warp_m + mi * 16 + g;
#pragma unroll
        for (int ni = 0; ni < 8; ni++) {
            int cb = col0 + warp_n + ni * 8 + t2;
            float b0 = bias[cb], b1 = bias[cb + 1];
            if (r0 < NN) {
                float2 v = make_float2(acc[mi][ni][0] + b0, acc[mi][ni][1] + b1);
                *reinterpret_cast<float2*>(&g_y[(size_t)r0 * DD + cb]) = v;
            }
            if (r0 + 8 < NN) {
                float2 v = make_float2(acc[mi][ni][2] + b0, acc[mi][ni][3] + b1);
                *reinterpret_cast<float2*>(&g_y[(size_t)(r0 + 8) * DD + cb]) = v;
            }
        }
    }
}

// ---------------- Kernel F: warp-per-node CSR gather aggregation + residual update
__global__ void k_aggregate(const float* __restrict__ x, float* __restrict__ out) {
    int warp = (blockIdx.x * blockDim.x + threadIdx.x) >> 5;
    int lane = threadIdx.x & 31;
    if (warp >= NN) return;
    int n = warp;
    float dm = g_diagmaps[n];
    float diag = dm / (dm + 1.0f);   // == d_inv * diag_maps * d_inv

    const float4* yn = reinterpret_cast<const float4*>(g_y + (size_t)n * DD);
    float4 acc[4];
#pragma unroll
    for (int i = 0; i < 4; i++) {
        float4 v = yn[lane + 32 * i];
        acc[i].x = diag * v.x;
        acc[i].y = diag * v.y;
        acc[i].z = diag * v.z;
        acc[i].w = diag * v.w;
    }
    int e0 = g_off[n], e1 = g_off[n + 1];
    for (int e = e0; e < e1; e++) {
        int c = g_csr_col[e];
        float w = g_csr_w[e];
        const float4* yc = reinterpret_cast<const float4*>(g_y + (size_t)c * DD);
#pragma unroll
        for (int i = 0; i < 4; i++) {
            float4 v = yc[lane + 32 * i];
            acc[i].x += w * v.x;
            acc[i].y += w * v.y;
            acc[i].z += w * v.z;
            acc[i].w += w * v.w;
        }
    }
    const float4* xr = reinterpret_cast<const float4*>(x + (size_t)n * DD);
    float4* o = reinterpret_cast<float4*>(out) + (size_t)n * (DD / 4);
#pragma unroll
    for (int i = 0; i < 4; i++) {
        float4 xv = xr[lane + 32 * i];
        float4 r;
        r.x = xv.x - 0.5f * acc[i].x;
        r.y = xv.y - 0.5f * acc[i].y;
        r.z = xv.z - 0.5f * acc[i].z;
        r.w = xv.w - 0.5f * acc[i].w;
        o[lane + 32 * i] = r;
    }
}

// ---------------- launch ----------------
extern "C" void kernel_launch(void* const* d_in, const int* in_sizes, int n_in,
                              void* d_out, int out_size) {
    const float* x    = (const float*)d_in[0];
    const float* W    = (const float*)d_in[1];
    const float* b    = (const float*)d_in[2];
    const float* ws   = (const float*)d_in[3];
    const int*   ei   = (const int*)d_in[4];   // [2, EE]: first EE = row, next EE = col
    const int*   ridx = (const int*)d_in[5];
    const int* rows = ei;
    const int* cols = ei + EE;
    float* out = (float*)d_out;

    k_node_st<<<(NN * 32 + 255) / 256, 256>>>(x, ws);          // s,t + x->fp16
    k_wconv<<<(DD * DD / 4 + 255) / 256, 256>>>(W);            // W->fp16

    dim3 ggrid(DD / BN, (NN + BM - 1) / BM);
    k_gemm<<<ggrid, 256>>>(b);

    k_edge_maps<<<(EE + 255) / 256, 256>>>(rows, cols);
    k_scan<<<1, 1024>>>();
    k_edge_scatter<<<(EE + 255) / 256, 256>>>(rows, cols, ridx);

    k_aggregate<<<(NN * 32 + 255) / 256, 256>>>(x, out);
}

// round 7
// speedup vs baseline: 1.4195x; 1.0634x over previous
#include <cuda_runtime.h>
#include <cuda_fp16.h>
#include <cstdint>

// Problem constants (fixed by setup_inputs)
#define NN 50000
#define DD 512
#define EE 200000

// ---------------- scratch (static __device__ arrays; no allocation) ----------------
__device__ __align__(16) __half g_yh[(size_t)NN * DD];    // y = x @ W^T + b (fp16, ~51 MB)
__device__ __align__(16) __half g_xh[(size_t)NN * DD];    // fp16 copy of x (~51.2 MB)
__device__ __align__(16) __half g_wh[(size_t)DD * DD];    // fp16 copy of W (0.5 MB)
__device__ float g_s[NN];
__device__ float g_t[NN];
__device__ float g_maps[EE];
__device__ float g_diagmaps[NN];
__device__ float g_dinv[NN];
__device__ int   g_deg[NN];
__device__ int   g_off[NN + 1];
__device__ int   g_cursor[NN];
__device__ int   g_csr_col[EE];
__device__ float g_csr_w[EE];

// ---------------- Kernel A: s = x@w1, t = x@w2 (warp per node); fp16 convert of x;
//                  also zero accumulators
__global__ void k_node_st(const float* __restrict__ x, const float* __restrict__ w_sheaf) {
    int warp = (blockIdx.x * blockDim.x + threadIdx.x) >> 5;
    int lane = threadIdx.x & 31;
    if (warp >= NN) return;
    const float4* xr = reinterpret_cast<const float4*>(x + (size_t)warp * DD);
    const float4* w1 = reinterpret_cast<const float4*>(w_sheaf);
    const float4* w2 = reinterpret_cast<const float4*>(w_sheaf + DD);
    __half2* xh = reinterpret_cast<__half2*>(g_xh + (size_t)warp * DD);
    float s = 0.f, t = 0.f;
#pragma unroll
    for (int i = 0; i < 4; i++) {
        float4 v = xr[lane + 32 * i];
        float4 a = w1[lane + 32 * i];
        float4 b = w2[lane + 32 * i];
        s += v.x * a.x + v.y * a.y + v.z * a.z + v.w * a.w;
        t += v.x * b.x + v.y * b.y + v.z * b.z + v.w * b.w;
        int p = (lane + 32 * i) * 2;
        xh[p]     = __floats2half2_rn(v.x, v.y);
        xh[p + 1] = __floats2half2_rn(v.z, v.w);
    }
#pragma unroll
    for (int o = 16; o; o >>= 1) {
        s += __shfl_xor_sync(0xFFFFFFFFu, s, o);
        t += __shfl_xor_sync(0xFFFFFFFFu, t, o);
    }
    if (lane == 0) {
        g_s[warp] = s;
        g_t[warp] = t;
        g_diagmaps[warp] = 0.f;
        g_deg[warp] = 0;
    }
}

// ---------------- tiny kernel: W -> fp16
__global__ void k_wconv(const float* __restrict__ W) {
    int i = blockIdx.x * blockDim.x + threadIdx.x;   // over DD*DD/4
    const float4* src = reinterpret_cast<const float4*>(W);
    __half2* dst = reinterpret_cast<__half2*>(g_wh);
    float4 v = src[i];
    dst[2 * i]     = __floats2half2_rn(v.x, v.y);
    dst[2 * i + 1] = __floats2half2_rn(v.z, v.w);
}

// ---------------- Kernel B: per-edge maps + degree/diag accumulation
__global__ void k_edge_maps(const int* __restrict__ rows, const int* __restrict__ cols) {
    int e = blockIdx.x * blockDim.x + threadIdx.x;
    if (e >= EE) return;
    int r = rows[e], c = cols[e];
    float m = tanhf(g_s[r] + g_t[c]);
    g_maps[e] = m;
    atomicAdd(&g_diagmaps[r], m * m);
    atomicAdd(&g_deg[r], 1);
}

// ---------------- Kernel C: thread-chunked single-block scan -> CSR offsets + d_inv
__global__ __launch_bounds__(1024) void k_scan() {
    __shared__ int s_warp[32];
    const int CH = (NN + 1023) / 1024;  // 49
    int tid = threadIdx.x, lane = tid & 31, wid = tid >> 5;
    int base = tid * CH;
    int sum = 0;
#pragma unroll 7
    for (int i = 0; i < CH; i++) {
        int idx = base + i;
        if (idx < NN) sum += g_deg[idx];
    }
    int v = sum;
#pragma unroll
    for (int o = 1; o < 32; o <<= 1) {
        int y = __shfl_up_sync(0xFFFFFFFFu, v, o);
        if (lane >= o) v += y;
    }
    if (lane == 31) s_warp[wid] = v;
    __syncthreads();
    if (wid == 0) {
        int w = s_warp[lane];
#pragma unroll
        for (int o = 1; o < 32; o <<= 1) {
            int y = __shfl_up_sync(0xFFFFFFFFu, w, o);
            if (lane >= o) w += y;
        }
        s_warp[lane] = w;
    }
    __syncthreads();
    int run = v - sum + (wid ? s_warp[wid - 1] : 0);
    for (int i = 0; i < CH; i++) {
        int idx = base + i;
        if (idx < NN) {
            int d = g_deg[idx];
            g_off[idx] = run;
            g_cursor[idx] = run;
            g_dinv[idx] = rsqrtf(g_diagmaps[idx] + 1.0f);
            run += d;
        }
    }
    if (tid == 0) g_off[NN] = EE;
}

// ---------------- Kernel D: per-edge normalized weight + CSR scatter
__global__ void k_edge_scatter(const int* __restrict__ rows, const int* __restrict__ cols,
                               const int* __restrict__ ridx) {
    int e = blockIdx.x * blockDim.x + threadIdx.x;
    if (e >= EE) return;
    int r = rows[e], c = cols[e];
    float nm = -g_maps[e] * g_maps[ridx[e]] * g_dinv[r] * g_dinv[c];
    int pos = atomicAdd(&g_cursor[r], 1);
    g_csr_col[pos] = c;
    g_csr_w[pos] = nm;
}

// ========== GEMM: y = x @ W^T + b, fp16 mma.sync m16n8k16, cp.async double-buffered ====
__device__ __forceinline__ void mma_f16(float c[4], const uint32_t a[4], const uint32_t b[2]) {
    asm volatile(
        "mma.sync.aligned.m16n8k16.row.col.f32.f16.f16.f32 "
        "{%0,%1,%2,%3}, {%4,%5,%6,%7}, {%8,%9}, {%0,%1,%2,%3};\n"
        : "+f"(c[0]), "+f"(c[1]), "+f"(c[2]), "+f"(c[3])
        : "r"(a[0]), "r"(a[1]), "r"(a[2]), "r"(a[3]), "r"(b[0]), "r"(b[1]));
}

__device__ __forceinline__ void cp_async16(uint32_t s, const void* g, int src_size) {
    asm volatile("cp.async.cg.shared.global [%0], [%1], 16, %2;\n"
                 :: "r"(s), "l"(g), "r"(src_size));
}
__device__ __forceinline__ void cp_commit() { asm volatile("cp.async.commit_group;\n"); }
template <int W> __device__ __forceinline__ void cp_wait() {
    asm volatile("cp.async.wait_group %0;\n" :: "n"(W));
}

#define BM 128
#define BN 128
#define BK 32
#define HS 40                   // half stride per row: 32 + 8 pad (80B, bank-conflict-free)
#define STG_MAT (128 * HS)      // halves per matrix per stage
#define STG (2 * STG_MAT)       // halves per stage (A + B)

__device__ __forceinline__ void load_stage_f16(__half* Asm, __half* Bsm,
                                               const __half* __restrict__ A,
                                               const __half* __restrict__ W,
                                               int row0, int col0, int k0, int tid) {
    // each matrix tile: 128 rows x 32 halves = 64B/row = 4 x 16B chunks; 512 chunks
#pragma unroll
    for (int i = 0; i < 2; i++) {
        int q = tid + i * 256;          // 0..511
        int r = q >> 2;                 // 0..127
        int c8 = (q & 3) << 3;          // 0,8,16,24 (halves)
        int gr = row0 + r;
        int ok = (gr < NN);
        const __half* src_a = A + (size_t)(ok ? gr : 0) * DD + k0 + c8;
        cp_async16((uint32_t)__cvta_generic_to_shared(Asm + r * HS + c8), src_a, ok ? 16 : 0);
        const __half* src_b = W + (size_t)(col0 + r) * DD + k0 + c8;
        cp_async16((uint32_t)__cvta_generic_to_shared(Bsm + r * HS + c8), src_b, 16);
    }
}

__global__ __launch_bounds__(256) void k_gemm(const float* __restrict__ bias) {
    __shared__ __half sm[2 * STG];
    int tid = threadIdx.x;
    int wid = tid >> 5, lane = tid & 31;
    int row0 = blockIdx.y * BM;
    int col0 = blockIdx.x * BN;

    int warp_m = (wid & 3) * 32;   // 4 warps along M -> 128
    int warp_n = (wid >> 2) * 64;  // 2 warps along N -> 128
    int g = lane >> 2;             // 0..7
    int t2 = (lane & 3) * 2;       // 0,2,4,6

    float acc[2][8][4];
#pragma unroll
    for (int mi = 0; mi < 2; mi++)
#pragma unroll
        for (int ni = 0; ni < 8; ni++)
#pragma unroll
            for (int q = 0; q < 4; q++) acc[mi][ni][q] = 0.f;

    const int NIT = DD / BK;  // 16
    load_stage_f16(sm, sm + STG_MAT, g_xh, g_wh, row0, col0, 0, tid);
    cp_commit();

    for (int it = 0; it < NIT; it++) {
        if (it + 1 < NIT) {
            __half* base = sm + ((it + 1) & 1) * STG;
            load_stage_f16(base, base + STG_MAT, g_xh, g_wh, row0, col0, (it + 1) * BK, tid);
            cp_commit();
            cp_wait<1>();
        } else {
            cp_wait<0>();
        }
        __syncthreads();

        const __half* Asb = sm + (it & 1) * STG;
        const __half* Bsb = Asb + STG_MAT;

#pragma unroll
        for (int kk = 0; kk < BK; kk += 16) {
            uint32_t afrag[2][4];
#pragma unroll
            for (int mi = 0; mi < 2; mi++) {
                int mrow = warp_m + mi * 16 + g;
                int kc = kk + t2;
                afrag[mi][0] = *reinterpret_cast<const uint32_t*>(&Asb[mrow * HS + kc]);
                afrag[mi][1] = *reinterpret_cast<const uint32_t*>(&Asb[(mrow + 8) * HS + kc]);
                afrag[mi][2] = *reinterpret_cast<const uint32_t*>(&Asb[mrow * HS + kc + 8]);
                afrag[mi][3] = *reinterpret_cast<const uint32_t*>(&Asb[(mrow + 8) * HS + kc + 8]);
            }
            uint32_t bfrag[8][2];
#pragma unroll
            for (int ni = 0; ni < 8; ni++) {
                int nrow = warp_n + ni * 8 + g;
                int kc = kk + t2;
                bfrag[ni][0] = *reinterpret_cast<const uint32_t*>(&Bsb[nrow * HS + kc]);
                bfrag[ni][1] = *reinterpret_cast<const uint32_t*>(&Bsb[nrow * HS + kc + 8]);
            }
#pragma unroll
            for (int mi = 0; mi < 2; mi++)
#pragma unroll
                for (int ni = 0; ni < 8; ni++) mma_f16(acc[mi][ni], afrag[mi], bfrag[ni]);
        }
        __syncthreads();
    }

    // epilogue: add bias, convert to fp16, store to g_yh
#pragma unroll
    for (int mi = 0; mi < 2; mi++) {
        int r0 = row0 + warp_m + mi * 16 + g;
#pragma unroll
        for (int ni = 0; ni < 8; ni++) {
            int cb = col0 + warp_n + ni * 8 + t2;
            float b0 = bias[cb], b1 = bias[cb + 1];
            if (r0 < NN) {
                *reinterpret_cast<__half2*>(&g_yh[(size_t)r0 * DD + cb]) =
                    __floats2half2_rn(acc[mi][ni][0] + b0, acc[mi][ni][1] + b1);
            }
            if (r0 + 8 < NN) {
                *reinterpret_cast<__half2*>(&g_yh[(size_t)(r0 + 8) * DD + cb]) =
                    __floats2half2_rn(acc[mi][ni][2] + b0, acc[mi][ni][3] + b1);
            }
        }
    }
}

// ---------------- Kernel F: warp-per-node CSR gather aggregation + residual update
__device__ __forceinline__ void unpack8(const uint4& u, float* f) {
    float2 p;
    p = __half22float2(*reinterpret_cast<const __half2*>(&u.x)); f[0] = p.x; f[1] = p.y;
    p = __half22float2(*reinterpret_cast<const __half2*>(&u.y)); f[2] = p.x; f[3] = p.y;
    p = __half22float2(*reinterpret_cast<const __half2*>(&u.z)); f[4] = p.x; f[5] = p.y;
    p = __half22float2(*reinterpret_cast<const __half2*>(&u.w)); f[6] = p.x; f[7] = p.y;
}

__global__ void k_aggregate(const float* __restrict__ x, float* __restrict__ out) {
    int warp = (blockIdx.x * blockDim.x + threadIdx.x) >> 5;
    int lane = threadIdx.x & 31;
    if (warp >= NN) return;
    int n = warp;
    float dm = g_diagmaps[n];
    float diag = dm / (dm + 1.0f);   // == d_inv * diag_maps * d_inv

    // lane covers cols [lane*16, lane*16+16) = 2 uint4 (16 halves)
    const uint4* yn = reinterpret_cast<const uint4*>(g_yh + (size_t)n * DD) + lane * 2;
    float acc[16], tmp[16];
    {
        uint4 u0 = yn[0], u1 = yn[1];
        unpack8(u0, acc);
        unpack8(u1, acc + 8);
#pragma unroll
        for (int j = 0; j < 16; j++) acc[j] *= diag;
    }
    int e0 = g_off[n], e1 = g_off[n + 1];
    for (int e = e0; e < e1; e++) {
        int c = g_csr_col[e];
        float w = g_csr_w[e];
        const uint4* yc = reinterpret_cast<const uint4*>(g_yh + (size_t)c * DD) + lane * 2;
        uint4 u0 = yc[0], u1 = yc[1];
        unpack8(u0, tmp);
        unpack8(u1, tmp + 8);
#pragma unroll
        for (int j = 0; j < 16; j++) acc[j] += w * tmp[j];
    }
    const float4* xr = reinterpret_cast<const float4*>(x + (size_t)n * DD) + lane * 4;
    float4* o = reinterpret_cast<float4*>(out) + (size_t)n * (DD / 4) + lane * 4;
#pragma unroll
    for (int i = 0; i < 4; i++) {
        float4 xv = xr[i];
        float4 r;
        r.x = xv.x - 0.5f * acc[4 * i + 0];
        r.y = xv.y - 0.5f * acc[4 * i + 1];
        r.z = xv.z - 0.5f * acc[4 * i + 2];
        r.w = xv.w - 0.5f * acc[4 * i + 3];
        o[i] = r;
    }
}

// ---------------- launch ----------------
extern "C" void kernel_launch(void* const* d_in, const int* in_sizes, int n_in,
                              void* d_out, int out_size) {
    const float* x    = (const float*)d_in[0];
    const float* W    = (const float*)d_in[1];
    const float* b    = (const float*)d_in[2];
    const float* ws   = (const float*)d_in[3];
    const int*   ei   = (const int*)d_in[4];   // [2, EE]: first EE = row, next EE = col
    const int*   ridx = (const int*)d_in[5];
    const int* rows = ei;
    const int* cols = ei + EE;
    float* out = (float*)d_out;

    // order chosen so k_gemm is launch index 3 (the one ncu samples)
    k_node_st<<<(NN * 32 + 255) / 256, 256>>>(x, ws);          // s,t + x->fp16
    k_wconv<<<(DD * DD / 4 + 255) / 256, 256>>>(W);            // W->fp16
    k_edge_maps<<<(EE + 255) / 256, 256>>>(rows, cols);

    dim3 ggrid(DD / BN, (NN + BM - 1) / BM);
    k_gemm<<<ggrid, 256>>>(b);

    k_scan<<<1, 1024>>>();
    k_edge_scatter<<<(EE + 255) / 256, 256>>>(rows, cols, ridx);

    k_aggregate<<<(NN * 32 + 255) / 256, 256>>>(x, out);
}

// round 8
// speedup vs baseline: 1.4790x; 1.0419x over previous
#include <cuda_runtime.h>
#include <cuda_fp16.h>
#include <cstdint>

// Problem constants (fixed by setup_inputs)
#define NN 50000
#define DD 512
#define EE 200000

// ---------------- scratch (static __device__ arrays; no allocation) ----------------
__device__ __align__(16) __half g_yh[(size_t)NN * DD];    // y = x @ W^T + b (fp16, ~51 MB)
__device__ __align__(16) __half g_xh[(size_t)NN * DD];    // fp16 copy of x (~51.2 MB)
__device__ __align__(16) __half g_wh[(size_t)DD * DD];    // fp16 copy of W (0.5 MB)
__device__ float g_s[NN];
__device__ float g_t[NN];
__device__ float g_maps[EE];
__device__ float g_diagmaps[NN];
__device__ float g_dinv[NN];
__device__ int   g_deg[NN];
__device__ int   g_off[NN + 1];
__device__ int   g_cursor[NN];
__device__ int   g_csr_col[EE];
__device__ float g_csr_w[EE];

// ---------------- Kernel A: s = x@w1, t = x@w2 (warp per node); fp16 convert of x;
//                  also zero accumulators
__global__ void k_node_st(const float* __restrict__ x, const float* __restrict__ w_sheaf) {
    int warp = (blockIdx.x * blockDim.x + threadIdx.x) >> 5;
    int lane = threadIdx.x & 31;
    if (warp >= NN) return;
    const float4* xr = reinterpret_cast<const float4*>(x + (size_t)warp * DD);
    const float4* w1 = reinterpret_cast<const float4*>(w_sheaf);
    const float4* w2 = reinterpret_cast<const float4*>(w_sheaf + DD);
    __half2* xh = reinterpret_cast<__half2*>(g_xh + (size_t)warp * DD);
    float s = 0.f, t = 0.f;
#pragma unroll
    for (int i = 0; i < 4; i++) {
        float4 v = xr[lane + 32 * i];
        float4 a = w1[lane + 32 * i];
        float4 b = w2[lane + 32 * i];
        s += v.x * a.x + v.y * a.y + v.z * a.z + v.w * a.w;
        t += v.x * b.x + v.y * b.y + v.z * b.z + v.w * b.w;
        int p = (lane + 32 * i) * 2;
        xh[p]     = __floats2half2_rn(v.x, v.y);
        xh[p + 1] = __floats2half2_rn(v.z, v.w);
    }
#pragma unroll
    for (int o = 16; o; o >>= 1) {
        s += __shfl_xor_sync(0xFFFFFFFFu, s, o);
        t += __shfl_xor_sync(0xFFFFFFFFu, t, o);
    }
    if (lane == 0) {
        g_s[warp] = s;
        g_t[warp] = t;
        g_diagmaps[warp] = 0.f;
        g_deg[warp] = 0;
    }
}

// ---------------- tiny kernel: W -> fp16
__global__ void k_wconv(const float* __restrict__ W) {
    int i = blockIdx.x * blockDim.x + threadIdx.x;   // over DD*DD/4
    const float4* src = reinterpret_cast<const float4*>(W);
    __half2* dst = reinterpret_cast<__half2*>(g_wh);
    float4 v = src[i];
    dst[2 * i]     = __floats2half2_rn(v.x, v.y);
    dst[2 * i + 1] = __floats2half2_rn(v.z, v.w);
}

// ---------------- Kernel B: per-edge maps + degree/diag accumulation
__global__ void k_edge_maps(const int* __restrict__ rows, const int* __restrict__ cols) {
    int e = blockIdx.x * blockDim.x + threadIdx.x;
    if (e >= EE) return;
    int r = rows[e], c = cols[e];
    float m = tanhf(g_s[r] + g_t[c]);
    g_maps[e] = m;
    atomicAdd(&g_diagmaps[r], m * m);
    atomicAdd(&g_deg[r], 1);
}

// ---------------- Kernel C: thread-chunked single-block scan -> CSR offsets + d_inv
__global__ __launch_bounds__(1024) void k_scan() {
    __shared__ int s_warp[32];
    const int CH = (NN + 1023) / 1024;  // 49
    int tid = threadIdx.x, lane = tid & 31, wid = tid >> 5;
    int base = tid * CH;
    int sum = 0;
#pragma unroll 7
    for (int i = 0; i < CH; i++) {
        int idx = base + i;
        if (idx < NN) sum += g_deg[idx];
    }
    int v = sum;
#pragma unroll
    for (int o = 1; o < 32; o <<= 1) {
        int y = __shfl_up_sync(0xFFFFFFFFu, v, o);
        if (lane >= o) v += y;
    }
    if (lane == 31) s_warp[wid] = v;
    __syncthreads();
    if (wid == 0) {
        int w = s_warp[lane];
#pragma unroll
        for (int o = 1; o < 32; o <<= 1) {
            int y = __shfl_up_sync(0xFFFFFFFFu, w, o);
            if (lane >= o) w += y;
        }
        s_warp[lane] = w;
    }
    __syncthreads();
    int run = v - sum + (wid ? s_warp[wid - 1] : 0);
    for (int i = 0; i < CH; i++) {
        int idx = base + i;
        if (idx < NN) {
            int d = g_deg[idx];
            g_off[idx] = run;
            g_cursor[idx] = run;
            g_dinv[idx] = rsqrtf(g_diagmaps[idx] + 1.0f);
            run += d;
        }
    }
    if (tid == 0) g_off[NN] = EE;
}

// ---------------- Kernel D: per-edge normalized weight + CSR scatter
__global__ void k_edge_scatter(const int* __restrict__ rows, const int* __restrict__ cols,
                               const int* __restrict__ ridx) {
    int e = blockIdx.x * blockDim.x + threadIdx.x;
    if (e >= EE) return;
    int r = rows[e], c = cols[e];
    float nm = -g_maps[e] * g_maps[ridx[e]] * g_dinv[r] * g_dinv[c];
    int pos = atomicAdd(&g_cursor[r], 1);
    g_csr_col[pos] = c;
    g_csr_w[pos] = nm;
}

// ========== GEMM: y = x @ W^T + b, fp16 mma.sync m16n8k16 + ldmatrix ====
__device__ __forceinline__ void mma_f16(float c[4], const uint32_t a[4], const uint32_t b[2]) {
    asm volatile(
        "mma.sync.aligned.m16n8k16.row.col.f32.f16.f16.f32 "
        "{%0,%1,%2,%3}, {%4,%5,%6,%7}, {%8,%9}, {%0,%1,%2,%3};\n"
        : "+f"(c[0]), "+f"(c[1]), "+f"(c[2]), "+f"(c[3])
        : "r"(a[0]), "r"(a[1]), "r"(a[2]), "r"(a[3]), "r"(b[0]), "r"(b[1]));
}

__device__ __forceinline__ void ldsm_x4(uint32_t& r0, uint32_t& r1, uint32_t& r2, uint32_t& r3,
                                        uint32_t addr) {
    asm volatile("ldmatrix.sync.aligned.m8n8.x4.shared.b16 {%0,%1,%2,%3}, [%4];"
                 : "=r"(r0), "=r"(r1), "=r"(r2), "=r"(r3) : "r"(addr));
}

__device__ __forceinline__ void cp_async16(uint32_t s, const void* g, int src_size) {
    asm volatile("cp.async.cg.shared.global [%0], [%1], 16, %2;\n"
                 :: "r"(s), "l"(g), "r"(src_size));
}
__device__ __forceinline__ void cp_commit() { asm volatile("cp.async.commit_group;\n"); }
template <int W> __device__ __forceinline__ void cp_wait() {
    asm volatile("cp.async.wait_group %0;\n" :: "n"(W));
}

#define BM 128
#define BN 128
#define BK 32
#define HS 40                   // half stride per row: 32 + 8 pad (80B, conflict-free LDSM)
#define STG_MAT (128 * HS)      // halves per matrix per stage
#define STG (2 * STG_MAT)       // halves per stage (A + B)

__device__ __forceinline__ void load_stage_f16(__half* Asm, __half* Bsm,
                                               const __half* __restrict__ A,
                                               const __half* __restrict__ W,
                                               int row0, int col0, int k0, int tid) {
    // each matrix tile: 128 rows x 32 halves = 64B/row = 4 x 16B chunks; 512 chunks
#pragma unroll
    for (int i = 0; i < 2; i++) {
        int q = tid + i * 256;          // 0..511
        int r = q >> 2;                 // 0..127
        int c8 = (q & 3) << 3;          // 0,8,16,24 (halves)
        int gr = row0 + r;
        int ok = (gr < NN);
        const __half* src_a = A + (size_t)(ok ? gr : 0) * DD + k0 + c8;
        cp_async16((uint32_t)__cvta_generic_to_shared(Asm + r * HS + c8), src_a, ok ? 16 : 0);
        const __half* src_b = W + (size_t)(col0 + r) * DD + k0 + c8;
        cp_async16((uint32_t)__cvta_generic_to_shared(Bsm + r * HS + c8), src_b, 16);
    }
}

__global__ __launch_bounds__(256) void k_gemm(const float* __restrict__ bias) {
    __shared__ __half sm[2 * STG];
    const uint32_t smb = (uint32_t)__cvta_generic_to_shared(sm);
    int tid = threadIdx.x;
    int wid = tid >> 5, lane = tid & 31;
    int row0 = blockIdx.y * BM;
    int col0 = blockIdx.x * BN;

    int warp_m = (wid & 3) * 32;   // 4 warps along M -> 128
    int warp_n = (wid >> 2) * 64;  // 2 warps along N -> 128
    int g = lane >> 2;             // 0..7
    int t2 = (lane & 3) * 2;       // 0,2,4,6

    // ldmatrix per-lane source coordinates (within tile, in halves)
    int a_r = warp_m + (lane & 15);            // row for A ldsm
    int a_c = (lane >> 4) << 3;                // 0 or 8
    uint32_t a_base = (uint32_t)(a_r * HS + a_c) * 2;
    int b_r = warp_n + (lane & 7) + ((lane >> 4) << 3);  // n-row for B ldsm
    int b_c = ((lane >> 3) & 1) << 3;          // 0 or 8
    uint32_t b_base = (uint32_t)(b_r * HS + b_c) * 2 + STG_MAT * 2;

    float acc[2][8][4];
#pragma unroll
    for (int mi = 0; mi < 2; mi++)
#pragma unroll
        for (int ni = 0; ni < 8; ni++)
#pragma unroll
            for (int q = 0; q < 4; q++) acc[mi][ni][q] = 0.f;

    const int NIT = DD / BK;  // 16
    load_stage_f16(sm, sm + STG_MAT, g_xh, g_wh, row0, col0, 0, tid);
    cp_commit();

    for (int it = 0; it < NIT; it++) {
        if (it + 1 < NIT) {
            __half* base = sm + ((it + 1) & 1) * STG;
            load_stage_f16(base, base + STG_MAT, g_xh, g_wh, row0, col0, (it + 1) * BK, tid);
            cp_commit();
            cp_wait<1>();
        } else {
            cp_wait<0>();
        }
        __syncthreads();

        uint32_t stg_off = smb + (uint32_t)(it & 1) * (STG * 2);

#pragma unroll
        for (int kk = 0; kk < BK; kk += 16) {
            uint32_t kb = (uint32_t)kk * 2;
            uint32_t afrag[2][4];
#pragma unroll
            for (int mi = 0; mi < 2; mi++)
                ldsm_x4(afrag[mi][0], afrag[mi][1], afrag[mi][2], afrag[mi][3],
                        stg_off + a_base + (uint32_t)(mi * 16 * HS) * 2 + kb);
            uint32_t bfrag[8][2];
#pragma unroll
            for (int p = 0; p < 4; p++)
                ldsm_x4(bfrag[2 * p][0], bfrag[2 * p][1], bfrag[2 * p + 1][0], bfrag[2 * p + 1][1],
                        stg_off + b_base + (uint32_t)(p * 16 * HS) * 2 + kb);
#pragma unroll
            for (int mi = 0; mi < 2; mi++)
#pragma unroll
                for (int ni = 0; ni < 8; ni++) mma_f16(acc[mi][ni], afrag[mi], bfrag[ni]);
        }
        __syncthreads();
    }

    // epilogue: add bias, convert to fp16, store to g_yh
#pragma unroll
    for (int mi = 0; mi < 2; mi++) {
        int r0 = row0 + warp_m + mi * 16 + g;
#pragma unroll
        for (int ni = 0; ni < 8; ni++) {
            int cb = col0 + warp_n + ni * 8 + t2;
            float b0 = bias[cb], b1 = bias[cb + 1];
            if (r0 < NN) {
                *reinterpret_cast<__half2*>(&g_yh[(size_t)r0 * DD + cb]) =
                    __floats2half2_rn(acc[mi][ni][0] + b0, acc[mi][ni][1] + b1);
            }
            if (r0 + 8 < NN) {
                *reinterpret_cast<__half2*>(&g_yh[(size_t)(r0 + 8) * DD + cb]) =
                    __floats2half2_rn(acc[mi][ni][2] + b0, acc[mi][ni][3] + b1);
            }
        }
    }
}

// ---------------- Kernel F: warp-per-node CSR gather aggregation + residual update
__device__ __forceinline__ void unpack8(const uint4& u, float* f) {
    float2 p;
    p = __half22float2(*reinterpret_cast<const __half2*>(&u.x)); f[0] = p.x; f[1] = p.y;
    p = __half22float2(*reinterpret_cast<const __half2*>(&u.y)); f[2] = p.x; f[3] = p.y;
    p = __half22float2(*reinterpret_cast<const __half2*>(&u.z)); f[4] = p.x; f[5] = p.y;
    p = __half22float2(*reinterpret_cast<const __half2*>(&u.w)); f[6] = p.x; f[7] = p.y;
}

__global__ void k_aggregate(const float* __restrict__ x, float* __restrict__ out) {
    int warp = (blockIdx.x * blockDim.x + threadIdx.x) >> 5;
    int lane = threadIdx.x & 31;
    if (warp >= NN) return;
    int n = warp;
    float dm = g_diagmaps[n];
    float diag = dm / (dm + 1.0f);   // == d_inv * diag_maps * d_inv

    // lane covers cols [lane*16, lane*16+16) = 2 uint4 (16 halves)
    const uint4* yn = reinterpret_cast<const uint4*>(g_yh + (size_t)n * DD) + lane * 2;
    float acc[16], tmp[16];
    {
        uint4 u0 = yn[0], u1 = yn[1];
        unpack8(u0, acc);
        unpack8(u1, acc + 8);
#pragma unroll
        for (int j = 0; j < 16; j++) acc[j] *= diag;
    }
    int e0 = g_off[n], e1 = g_off[n + 1];
    for (int e = e0; e < e1; e++) {
        int c = g_csr_col[e];
        float w = g_csr_w[e];
        const uint4* yc = reinterpret_cast<const uint4*>(g_yh + (size_t)c * DD) + lane * 2;
        uint4 u0 = yc[0], u1 = yc[1];
        unpack8(u0, tmp);
        unpack8(u1, tmp + 8);
#pragma unroll
        for (int j = 0; j < 16; j++) acc[j] += w * tmp[j];
    }
    const float4* xr = reinterpret_cast<const float4*>(x + (size_t)n * DD) + lane * 4;
    float4* o = reinterpret_cast<float4*>(out) + (size_t)n * (DD / 4) + lane * 4;
#pragma unroll
    for (int i = 0; i < 4; i++) {
        float4 xv = xr[i];
        float4 r;
        r.x = xv.x - 0.5f * acc[4 * i + 0];
        r.y = xv.y - 0.5f * acc[4 * i + 1];
        r.z = xv.z - 0.5f * acc[4 * i + 2];
        r.w = xv.w - 0.5f * acc[4 * i + 3];
        o[i] = r;
    }
}

// ---------------- launch ----------------
extern "C" void kernel_launch(void* const* d_in, const int* in_sizes, int n_in,
                              void* d_out, int out_size) {
    const float* x    = (const float*)d_in[0];
    const float* W    = (const float*)d_in[1];
    const float* b    = (const float*)d_in[2];
    const float* ws   = (const float*)d_in[3];
    const int*   ei   = (const int*)d_in[4];   // [2, EE]: first EE = row, next EE = col
    const int*   ridx = (const int*)d_in[5];
    const int* rows = ei;
    const int* cols = ei + EE;
    float* out = (float*)d_out;

    // order chosen so k_gemm is launch index 3 (the one ncu samples)
    k_node_st<<<(NN * 32 + 255) / 256, 256>>>(x, ws);          // s,t + x->fp16
    k_wconv<<<(DD * DD / 4 + 255) / 256, 256>>>(W);            // W->fp16
    k_edge_maps<<<(EE + 255) / 256, 256>>>(rows, cols);

    dim3 ggrid(DD / BN, (NN + BM - 1) / BM);
    k_gemm<<<ggrid, 256>>>(b);

    k_scan<<<1, 1024>>>();
    k_edge_scatter<<<(EE + 255) / 256, 256>>>(rows, cols, ridx);

    k_aggregate<<<(NN * 32 + 255) / 256, 256>>>(x, out);
}